// round 1
// baseline (speedup 1.0000x reference)
#include <cuda_runtime.h>
#include <cuda_bf16.h>
#include <math.h>

// ---------------- problem constants ----------------
#define BB 2
#define NN_NODES 512
#define FDIM 1024
#define HEADS 4
#define DH 256
#define AH 256
#define HID 512
#define OUTF 128
#define NCLS 10
#define NN2 (NN_NODES*NN_NODES)          // 262144
#define KSEL 209715                       // int(0.8 * N*N)
#define THR_IDX (NN2 - KSEL)              // 52429 (0-based ascending)
#define BN_M (BB*NN_NODES)                // 1024 rows for batchnorm

// ---------------- device scratch (no allocations allowed) ----------------
__device__ float g_hp [BB*NN_NODES*FDIM];     // x @ Wg^T         4MB
__device__ float g_nf [BB*NN_NODES*FDIM];     // node feats       4MB
__device__ float g_si [BB*HEADS*NN_NODES];
__device__ float g_sj [BB*HEADS*NN_NODES];
__device__ float g_pi [BB*NN_NODES*AH];       // 1MB
__device__ float g_pj [BB*NN_NODES*AH];       // 1MB
__device__ float g_sc [BB*NN2];               // scores -> softmax 2MB
__device__ float g_adj[BB*NN2];               // causal adj       2MB
__device__ float g_h1 [BB*NN_NODES*FDIM];     // adj@nf           4MB
__device__ float g_h1b[BB*NN_NODES*HID];      // gc1 out          2MB
__device__ float g_h2 [BB*NN_NODES*HID];      // adj@h1b          2MB
__device__ float g_h2b[BB*NN_NODES*OUTF];     // gc2 out          0.5MB
__device__ float g_part[BB*256];
__device__ float g_mx[BB];
__device__ float g_S [BB];
__device__ float g_thr[BB];
__device__ float g_selsum[BB];

// ---------------- generic tiled GEMM ----------------
// C[m,n] = sum_k A[m,k] * (TRANSB ? B[n,k] : B[k,n])  (+ bias[n])
// block 256 threads, tile 64x64, K-tile 32. M%64==0, N%64==0, K%32==0.
template<bool TRANSB, bool BIAS>
__global__ void gemm_kernel(const float* __restrict__ A, int lda, long sA,
                            const float* __restrict__ Bm, int ldb, long sB,
                            const float* __restrict__ bias,
                            float* __restrict__ C, int ldc, long sC,
                            int M, int Nc, int K)
{
    __shared__ float As[32][65];
    __shared__ float Bs[32][65];
    const int bz = blockIdx.z;
    A  += (long)bz * sA;
    Bm += (long)bz * sB;
    C  += (long)bz * sC;
    const int m0 = blockIdx.y * 64;
    const int n0 = blockIdx.x * 64;
    const int tid = threadIdx.x;
    const int tx = tid & 15, ty = tid >> 4;

    float acc[4][4];
#pragma unroll
    for (int i = 0; i < 4; i++)
#pragma unroll
        for (int j = 0; j < 4; j++) acc[i][j] = 0.f;

    for (int k0 = 0; k0 < K; k0 += 32) {
#pragma unroll
        for (int l = 0; l < 8; l++) {
            int idx = tid + l * 256;
            int m = idx >> 5, k = idx & 31;
            As[k][m] = A[(long)(m0 + m) * lda + k0 + k];
        }
        if (TRANSB) {
#pragma unroll
            for (int l = 0; l < 8; l++) {
                int idx = tid + l * 256;
                int n = idx >> 5, k = idx & 31;
                Bs[k][n] = Bm[(long)(n0 + n) * ldb + k0 + k];
            }
        } else {
#pragma unroll
            for (int l = 0; l < 8; l++) {
                int idx = tid + l * 256;
                int k = idx >> 6, n = idx & 63;
                Bs[k][n] = Bm[(long)(k0 + k) * ldb + n0 + n];
            }
        }
        __syncthreads();
#pragma unroll
        for (int k = 0; k < 32; k++) {
            float a[4], b[4];
#pragma unroll
            for (int i = 0; i < 4; i++) a[i] = As[k][ty * 4 + i];
#pragma unroll
            for (int j = 0; j < 4; j++) b[j] = Bs[k][tx * 4 + j];
#pragma unroll
            for (int i = 0; i < 4; i++)
#pragma unroll
                for (int j = 0; j < 4; j++) acc[i][j] += a[i] * b[j];
        }
        __syncthreads();
    }
#pragma unroll
    for (int i = 0; i < 4; i++) {
        int m = m0 + ty * 4 + i;
#pragma unroll
        for (int j = 0; j < 4; j++) {
            int n = n0 + tx * 4 + j;
            float v = acc[i][j];
            if (BIAS) v += bias[n];
            C[(long)m * ldc + n] = v;
        }
    }
}

// ---------------- s_i, s_j : per (b,h,n) dot over DH ----------------
__global__ void sij_kernel(const float* __restrict__ attn)
{
    int gw = (blockIdx.x * blockDim.x + threadIdx.x) >> 5;
    int lane = threadIdx.x & 31;
    if (gw >= BB * HEADS * NN_NODES) return;
    int b = gw / (HEADS * NN_NODES);
    int r = gw % (HEADS * NN_NODES);
    int h = r / NN_NODES;
    int n = r % NN_NODES;
    const float* hp = g_hp + ((long)(b * NN_NODES + n)) * FDIM + h * DH;
    const float* ai = attn + h * 2 * DH;
    float si = 0.f, sj = 0.f;
#pragma unroll
    for (int d = lane; d < DH; d += 32) {
        float v = hp[d];
        si += v * ai[d];
        sj += v * ai[DH + d];
    }
#pragma unroll
    for (int o = 16; o > 0; o >>= 1) {
        si += __shfl_down_sync(0xffffffffu, si, o);
        sj += __shfl_down_sync(0xffffffffu, sj, o);
    }
    if (lane == 0) { g_si[gw] = si; g_sj[gw] = sj; }
}

// ---------------- fused attention softmax + aggregation ----------------
// grid: (N/16, B*HEADS), 256 threads. Each block: 16 rows, all DH=256 cols.
__global__ void attn_kernel()
{
    __shared__ float sj[NN_NODES];
    __shared__ float w[16][NN_NODES];
    __shared__ float red[8];
    int bh = blockIdx.y;
    int b = bh / HEADS, h = bh % HEADS;
    int i0 = blockIdx.x * 16;
    int tid = threadIdx.x;

    for (int j = tid; j < NN_NODES; j += 256) sj[j] = g_sj[bh * NN_NODES + j];
    __syncthreads();

    // max_j sj
    float mx = -3.4e38f;
    for (int j = tid; j < NN_NODES; j += 256) mx = fmaxf(mx, sj[j]);
#pragma unroll
    for (int o = 16; o > 0; o >>= 1) mx = fmaxf(mx, __shfl_xor_sync(0xffffffffu, mx, o));
    if ((tid & 31) == 0) red[tid >> 5] = mx;
    __syncthreads();
    if (tid == 0) {
        float m = red[0];
        for (int q = 1; q < 8; q++) m = fmaxf(m, red[q]);
        red[0] = m;
    }
    __syncthreads();
    float sjmax = red[0];

    int wi = tid >> 5, lane = tid & 31;
#pragma unroll
    for (int rr = 0; rr < 2; rr++) {
        int r = wi * 2 + rr;
        int i = i0 + r;
        float si = g_si[bh * NN_NODES + i];
        float M = si + sjmax;
        M = (M >= 0.f) ? M : 0.2f * M;     // leaky is monotone -> max at sjmax
        float sum = 0.f;
        for (int j = lane; j < NN_NODES; j += 32) {
            float e = si + sj[j];
            e = (e >= 0.f) ? e : 0.2f * e;
            float p = expf(e - M);
            w[r][j] = p;
            sum += p;
        }
#pragma unroll
        for (int o = 16; o > 0; o >>= 1) sum += __shfl_xor_sync(0xffffffffu, sum, o);
        float inv = 1.0f / sum;
        for (int j = lane; j < NN_NODES; j += 32) w[r][j] *= inv;
    }
    __syncthreads();

    // aggregation: thread owns column d, 16 row accumulators
    int d = tid;
    const float* hp = g_hp + (long)(b * NN_NODES) * FDIM + h * DH + d;
    float acc[16];
#pragma unroll
    for (int r = 0; r < 16; r++) acc[r] = 0.f;
    for (int j = 0; j < NN_NODES; j++) {
        float v = hp[(long)j * FDIM];
#pragma unroll
        for (int r = 0; r < 16; r++) acc[r] += w[r][j] * v;
    }
#pragma unroll
    for (int r = 0; r < 16; r++)
        g_nf[((long)(b * NN_NODES) + i0 + r) * FDIM + h * DH + d] = acc[r];
}

// ---------------- edge MLP scores ----------------
// grid (N/16, N/16, B), 256 threads; thread = one (i,j) edge.
__global__ void edge_kernel(const float* __restrict__ b1,
                            const float* __restrict__ w2,
                            const float* __restrict__ b2p)
{
    __shared__ float spi[16][257];
    __shared__ float spj[16][257];
    __shared__ float sb1[AH];
    __shared__ float sw2[AH];
    int b = blockIdx.z;
    int i0 = blockIdx.y * 16, j0 = blockIdx.x * 16;
    int tid = threadIdx.x;
    if (tid < AH) { sb1[tid] = b1[tid]; sw2[tid] = w2[tid]; }
#pragma unroll
    for (int l = 0; l < 16; l++) {
        spi[l][tid] = g_pi[((long)(b * NN_NODES) + i0 + l) * AH + tid];
        spj[l][tid] = g_pj[((long)(b * NN_NODES) + j0 + l) * AH + tid];
    }
    __syncthreads();
    int ti = tid >> 4, tj = tid & 15;
    float acc = 0.f;
#pragma unroll 8
    for (int a = 0; a < AH; a++) {
        float t = spi[ti][a] + spj[tj][a] + sb1[a];
        acc += fmaxf(t, 0.f) * sw2[a];
    }
    float sc = (acc + b2p[0]) * 2.0f;   // /TEMP, TEMP=0.5
    g_sc[(long)b * NN2 + (long)(i0 + ti) * NN_NODES + (j0 + tj)] = sc;
}

// ---------------- deterministic two-stage reductions ----------------
__global__ void redmax_stage1()
{
    int b = blockIdx.y, blk = blockIdx.x, tid = threadIdx.x;
    const float* p = g_sc + (long)b * NN2;
    float mx = -3.4e38f;
    for (int i = blk * 256 + tid; i < NN2; i += 256 * 256) mx = fmaxf(mx, p[i]);
    __shared__ float sh[256];
    sh[tid] = mx; __syncthreads();
    for (int s = 128; s > 0; s >>= 1) { if (tid < s) sh[tid] = fmaxf(sh[tid], sh[tid + s]); __syncthreads(); }
    if (tid == 0) g_part[b * 256 + blk] = sh[0];
}
__global__ void redmax_stage2()
{
    int b = blockIdx.x, tid = threadIdx.x;
    __shared__ float sh[256];
    sh[tid] = g_part[b * 256 + tid]; __syncthreads();
    for (int s = 128; s > 0; s >>= 1) { if (tid < s) sh[tid] = fmaxf(sh[tid], sh[tid + s]); __syncthreads(); }
    if (tid == 0) g_mx[b] = sh[0];
}
__global__ void exp_stage1()
{
    int b = blockIdx.y, blk = blockIdx.x, tid = threadIdx.x;
    float* p = g_sc + (long)b * NN2;
    float mx = g_mx[b];
    float s = 0.f;
    for (int i = blk * 256 + tid; i < NN2; i += 256 * 256) {
        float v = expf(p[i] - mx);
        p[i] = v;
        s += v;
    }
    __shared__ float sh[256];
    sh[tid] = s; __syncthreads();
    for (int q = 128; q > 0; q >>= 1) { if (tid < q) sh[tid] += sh[tid + q]; __syncthreads(); }
    if (tid == 0) g_part[b * 256 + blk] = sh[0];
}
__global__ void sum_stage2()
{
    int b = blockIdx.x, tid = threadIdx.x;
    __shared__ float sh[256];
    sh[tid] = g_part[b * 256 + tid]; __syncthreads();
    for (int q = 128; q > 0; q >>= 1) { if (tid < q) sh[tid] += sh[tid + q]; __syncthreads(); }
    if (tid == 0) g_S[b] = sh[0];
}
__global__ void norm_kernel()
{
    int b = blockIdx.y, blk = blockIdx.x, tid = threadIdx.x;
    float* p = g_sc + (long)b * NN2;
    float S = g_S[b];
    for (int i = blk * 256 + tid; i < NN2; i += 256 * 256) p[i] = p[i] / S;
}

// ---------------- exact k-th order statistic via MSB radix select ----------------
// grid.x = B, 1024 threads. Finds sorted_ascending[THR_IDX].
__global__ void select_kernel()
{
    __shared__ unsigned hist[256];
    __shared__ unsigned s_prefix;
    __shared__ int s_rank;
    int b = blockIdx.x, tid = threadIdx.x;
    if (tid == 0) { s_prefix = 0u; s_rank = THR_IDX; }
    __syncthreads();
    const float* sm = g_sc + (long)b * NN2;
    for (int pass = 3; pass >= 0; pass--) {
        int shift = pass * 8;
        if (tid < 256) hist[tid] = 0u;
        __syncthreads();
        unsigned pref = s_prefix;
        unsigned mask = (pass == 3) ? 0u : (0xFFFFFFFFu << (shift + 8));
        for (int i = tid; i < NN2; i += 1024) {
            unsigned v = __float_as_uint(sm[i]);
            if ((v & mask) == pref) atomicAdd(&hist[(v >> shift) & 255], 1u);
        }
        __syncthreads();
        if (tid == 0) {
            int rank = s_rank;
            unsigned cum = 0; int bsel = 0;
            for (int x = 0; x < 256; x++) {
                if (cum + hist[x] > (unsigned)rank) { bsel = x; break; }
                cum += hist[x];
            }
            s_rank = rank - (int)cum;
            s_prefix = pref | ((unsigned)bsel << shift);
        }
        __syncthreads();
    }
    if (tid == 0) g_thr[b] = __uint_as_float(s_prefix);
}

__global__ void thresh_stage1()
{
    int b = blockIdx.y, blk = blockIdx.x, tid = threadIdx.x;
    const float* sm = g_sc + (long)b * NN2;
    float* adj = g_adj + (long)b * NN2;
    float thr = g_thr[b];
    float s = 0.f;
    for (int i = blk * 256 + tid; i < NN2; i += 256 * 256) {
        float v = sm[i];
        float keep = (v >= thr) ? v : 0.f;
        adj[i] = keep;
        s += keep;
    }
    __shared__ float sh[256];
    sh[tid] = s; __syncthreads();
    for (int q = 128; q > 0; q >>= 1) { if (tid < q) sh[tid] += sh[tid + q]; __syncthreads(); }
    if (tid == 0) g_part[b * 256 + blk] = sh[0];
}
__global__ void selsum_stage2()
{
    int b = blockIdx.x, tid = threadIdx.x;
    __shared__ float sh[256];
    sh[tid] = g_part[b * 256 + tid]; __syncthreads();
    for (int q = 128; q > 0; q >>= 1) { if (tid < q) sh[tid] += sh[tid + q]; __syncthreads(); }
    if (tid == 0) g_selsum[b] = sh[0];
}
__global__ void adjnorm_kernel()
{
    int b = blockIdx.y, blk = blockIdx.x, tid = threadIdx.x;
    float* adj = g_adj + (long)b * NN2;
    float denom = g_selsum[b] + 1e-12f;
    for (int i = blk * 256 + tid; i < NN2; i += 256 * 256) adj[i] = adj[i] / denom;
}

// ---------------- batchnorm (over B,N) + relu, in place ----------------
// grid.x = C/32, block (32,8)
__global__ void bn_relu_kernel(float* __restrict__ h,
                               const float* __restrict__ ga,
                               const float* __restrict__ be, int C)
{
    __shared__ float sh[8][32], sh2[8][32];
    int c = blockIdx.x * 32 + threadIdx.x;
    int ry = threadIdx.y;
    float s = 0.f, s2 = 0.f;
    for (int r = ry; r < BN_M; r += 8) {
        float v = h[(long)r * C + c];
        s += v; s2 += v * v;
    }
    sh[ry][threadIdx.x] = s; sh2[ry][threadIdx.x] = s2;
    __syncthreads();
    if (ry == 0) {
        for (int r = 1; r < 8; r++) { s += sh[r][threadIdx.x]; s2 += sh2[r][threadIdx.x]; }
        float m = s / (float)BN_M;
        float v = s2 / (float)BN_M - m * m;
        sh[0][threadIdx.x] = m;
        sh2[0][threadIdx.x] = rsqrtf(v + 1e-5f);
    }
    __syncthreads();
    float m = sh[0][threadIdx.x], inv = sh2[0][threadIdx.x];
    float gg = ga[c], bb = be[c];
    for (int r = ry; r < BN_M; r += 8) {
        float v = h[(long)r * C + c];
        h[(long)r * C + c] = fmaxf((v - m) * inv * gg + bb, 0.f);
    }
}

// ---------------- mean pool + classifier ----------------
__global__ void head_kernel(const float* __restrict__ cls_w,
                            const float* __restrict__ cls_b,
                            float* __restrict__ out)
{
    __shared__ float feat[OUTF];
    int b = blockIdx.x, tid = threadIdx.x; // 128 threads
    float s = 0.f;
    for (int r = 0; r < NN_NODES; r++) s += g_h2b[((long)b * NN_NODES + r) * OUTF + tid];
    feat[tid] = s / (float)NN_NODES;
    __syncthreads();
    if (tid < NCLS) {
        float acc = cls_b[tid];
        for (int f = 0; f < OUTF; f++) acc += feat[f] * cls_w[tid * OUTF + f];
        out[b * NCLS + tid] = acc;
    }
}

// ---------------- launcher ----------------
extern "C" void kernel_launch(void* const* d_in, const int* in_sizes, int n_in,
                              void* d_out, int out_size)
{
    const float* x     = (const float*)d_in[0];
    const float* Wg    = (const float*)d_in[1];
    const float* attn  = (const float*)d_in[2];
    const float* W1    = (const float*)d_in[3];
    const float* b1    = (const float*)d_in[4];
    const float* w2    = (const float*)d_in[5];
    const float* b2    = (const float*)d_in[6];
    const float* gc1_w = (const float*)d_in[7];
    const float* gc1_b = (const float*)d_in[8];
    const float* bn1_g = (const float*)d_in[9];
    const float* bn1_b = (const float*)d_in[10];
    const float* gc2_w = (const float*)d_in[11];
    const float* gc2_b = (const float*)d_in[12];
    const float* bn2_g = (const float*)d_in[13];
    const float* bn2_b = (const float*)d_in[14];
    const float* cls_w = (const float*)d_in[15];
    const float* cls_b = (const float*)d_in[16];
    float* out = (float*)d_out;

    float *hp, *nf, *pi, *pj, *adj, *h1, *h1b, *h2, *h2b;
    cudaGetSymbolAddress((void**)&hp,  g_hp);
    cudaGetSymbolAddress((void**)&nf,  g_nf);
    cudaGetSymbolAddress((void**)&pi,  g_pi);
    cudaGetSymbolAddress((void**)&pj,  g_pj);
    cudaGetSymbolAddress((void**)&adj, g_adj);
    cudaGetSymbolAddress((void**)&h1,  g_h1);
    cudaGetSymbolAddress((void**)&h1b, g_h1b);
    cudaGetSymbolAddress((void**)&h2,  g_h2);
    cudaGetSymbolAddress((void**)&h2b, g_h2b);

    // 1) hp = x @ Wg^T    (1024 x 1024 x 1024)
    gemm_kernel<true, false><<<dim3(16, 16, 1), 256>>>(
        x, FDIM, 0, Wg, FDIM, 0, nullptr, hp, FDIM, 0, BB * NN_NODES, FDIM, FDIM);

    // 2) s_i, s_j
    sij_kernel<<<(BB * HEADS * NN_NODES * 32 + 255) / 256, 256>>>(attn);

    // 3) attention softmax + aggregate -> node feats
    attn_kernel<<<dim3(NN_NODES / 16, BB * HEADS), 256>>>();

    // 4) pi = nf @ W1i^T, pj = nf @ W1j^T   (W1 rows have ld 2*FDIM)
    gemm_kernel<true, false><<<dim3(AH / 64, 16, 1), 256>>>(
        nf, FDIM, 0, W1, 2 * FDIM, 0, nullptr, pi, AH, 0, BB * NN_NODES, AH, FDIM);
    gemm_kernel<true, false><<<dim3(AH / 64, 16, 1), 256>>>(
        nf, FDIM, 0, W1 + FDIM, 2 * FDIM, 0, nullptr, pj, AH, 0, BB * NN_NODES, AH, FDIM);

    // 5) edge scores (already / TEMP)
    edge_kernel<<<dim3(NN_NODES / 16, NN_NODES / 16, BB), 256>>>(b1, w2, b2);

    // 6) flat softmax per batch (deterministic two-stage)
    redmax_stage1<<<dim3(256, BB), 256>>>();
    redmax_stage2<<<BB, 256>>>();
    exp_stage1<<<dim3(256, BB), 256>>>();
    sum_stage2<<<BB, 256>>>();
    norm_kernel<<<dim3(256, BB), 256>>>();

    // 7) exact threshold (k-th order statistic) + masked renormalize
    select_kernel<<<BB, 1024>>>();
    thresh_stage1<<<dim3(256, BB), 256>>>();
    selsum_stage2<<<BB, 256>>>();
    adjnorm_kernel<<<dim3(256, BB), 256>>>();

    // 8) h1 = adj @ nf  (batched, A*B)
    gemm_kernel<false, false><<<dim3(FDIM / 64, NN_NODES / 64, BB), 256>>>(
        adj, NN_NODES, (long)NN2, nf, FDIM, (long)NN_NODES * FDIM, nullptr,
        h1, FDIM, (long)NN_NODES * FDIM, NN_NODES, FDIM, NN_NODES);

    // 9) h1b = h1 @ gc1_w^T + gc1_b
    gemm_kernel<true, true><<<dim3(HID / 64, 16, 1), 256>>>(
        h1, FDIM, 0, gc1_w, FDIM, 0, gc1_b, h1b, HID, 0, BB * NN_NODES, HID, FDIM);

    // 10) bn1 + relu (in place)
    bn_relu_kernel<<<HID / 32, dim3(32, 8)>>>(h1b, bn1_g, bn1_b, HID);

    // 11) h2 = adj @ h1b  (batched)
    gemm_kernel<false, false><<<dim3(HID / 64, NN_NODES / 64, BB), 256>>>(
        adj, NN_NODES, (long)NN2, h1b, HID, (long)NN_NODES * HID, nullptr,
        h2, HID, (long)NN_NODES * HID, NN_NODES, HID, NN_NODES);

    // 12) h2b = h2 @ gc2_w^T + gc2_b
    gemm_kernel<true, true><<<dim3(OUTF / 64, 16, 1), 256>>>(
        h2, HID, 0, gc2_w, HID, 0, gc2_b, h2b, OUTF, 0, BB * NN_NODES, OUTF, HID);

    // 13) bn2 + relu (in place)
    bn_relu_kernel<<<OUTF / 32, dim3(32, 8)>>>(h2b, bn2_g, bn2_b, OUTF);

    // 14) mean pool + classifier
    head_kernel<<<BB, OUTF>>>(cls_w, cls_b, out);
}

// round 2
// speedup vs baseline: 1.8748x; 1.8748x over previous
#include <cuda_runtime.h>
#include <cuda_bf16.h>
#include <math.h>

// ---------------- problem constants ----------------
#define BB 2
#define NN_NODES 512
#define FDIM 1024
#define HEADS 4
#define DH 256
#define AH 256
#define HID 512
#define OUTF 128
#define NCLS 10
#define NN2 (NN_NODES*NN_NODES)          // 262144
#define KSEL 209715                       // int(0.8 * N*N)
#define THR_IDX (NN2 - KSEL)              // 52429 (0-based ascending)
#define BN_M (BB*NN_NODES)                // 1024 rows for batchnorm

// ---------------- device scratch (no allocations allowed) ----------------
__device__ float g_hp [BB*NN_NODES*FDIM];     // x @ Wg^T         4MB
__device__ float g_nf [BB*NN_NODES*FDIM];     // node feats       4MB
__device__ float g_si [BB*HEADS*NN_NODES];
__device__ float g_sj [BB*HEADS*NN_NODES];
__device__ float g_pi [BB*NN_NODES*AH];       // 1MB
__device__ float g_pj [BB*NN_NODES*AH];       // 1MB
__device__ float g_sc [BB*NN2];               // scores -> exp     2MB
__device__ float g_adj[BB*NN2];               // causal adj       2MB
__device__ float g_h1 [BB*NN_NODES*FDIM];     // adj@nf           4MB
__device__ float g_h1b[BB*NN_NODES*HID];      // gc1 out          2MB
__device__ float g_h2 [BB*NN_NODES*HID];      // adj@h1b          2MB
__device__ float g_h2b[BB*NN_NODES*OUTF];     // gc2 out          0.5MB
__device__ float g_part[BB*256];
__device__ float g_mx[BB];
__device__ float g_S [BB];
__device__ float g_thr[BB];
__device__ float g_selsum[BB];
__device__ unsigned g_hist[BB][256];
__device__ unsigned g_selpref[BB];
__device__ int g_selrank[BB];

// ---------------- tf32 helpers ----------------
__device__ __forceinline__ float f2tf32f(float x) {
    unsigned r;
    asm("cvt.rna.tf32.f32 %0, %1;" : "=r"(r) : "f"(x));
    return __uint_as_float(r);
}

// ---------------- tf32 tensor-core GEMM ----------------
// C[m,n] = sum_k A[m,k] * (TRANSB ? B[n,k] : B[k,n]) (+ bias[n])
// 128 threads, tile 64x64, K-tile 32, double-buffered smem.
// Requires M%64==0, N%64==0, K%32==0, lda/ldb multiples of 4.
#define APITCH 36
#define BPITCH 68
template<bool TRANSB, bool BIAS>
__global__ void mma_gemm(const float* __restrict__ A, int lda, long sA,
                         const float* __restrict__ Bm, int ldb, long sB,
                         const float* __restrict__ bias,
                         float* __restrict__ C, int ldc, long sC,
                         int K)
{
    __shared__ float As[2][64 * APITCH];
    __shared__ float Bs[2][32 * BPITCH];

    const int bz = blockIdx.z;
    A  += (long)bz * sA;
    Bm += (long)bz * sB;
    C  += (long)bz * sC;
    const int m0 = blockIdx.y * 64;
    const int n0 = blockIdx.x * 64;
    const int tid = threadIdx.x;
    const int lane = tid & 31;
    const int wid  = tid >> 5;
    const int wm = wid >> 1, wn = wid & 1;
    const int g  = lane >> 2;   // 0..7
    const int tg = lane & 3;    // 0..3

    // staging indices
    const int a_mr = tid >> 3;      // 0..15
    const int a_k4 = tid & 7;       // 0..7
    const int bt_nr = tid >> 3;     // 0..15 (TRANSB)
    const int bt_k4 = tid & 7;
    const int bn_kr = tid >> 4;     // 0..7  (non-trans)
    const int bn_n4 = tid & 15;

    float acc[2][4][4];
#pragma unroll
    for (int im = 0; im < 2; im++)
#pragma unroll
        for (int in = 0; in < 4; in++)
#pragma unroll
            for (int q = 0; q < 4; q++) acc[im][in][q] = 0.f;

    const int niter = K >> 5;

    // ---- prologue: load tile 0 directly ----
    {
        const int k0 = 0;
#pragma unroll
        for (int i = 0; i < 4; i++) {
            int m = a_mr + 16 * i;
            float4 v = *(const float4*)&A[(long)(m0 + m) * lda + k0 + a_k4 * 4];
            float4 w = make_float4(f2tf32f(v.x), f2tf32f(v.y), f2tf32f(v.z), f2tf32f(v.w));
            *(float4*)&As[0][m * APITCH + a_k4 * 4] = w;
        }
        if (TRANSB) {
#pragma unroll
            for (int i = 0; i < 4; i++) {
                int n = bt_nr + 16 * i;
                float4 v = *(const float4*)&Bm[(long)(n0 + n) * ldb + k0 + bt_k4 * 4];
                Bs[0][(bt_k4 * 4 + 0) * BPITCH + n] = f2tf32f(v.x);
                Bs[0][(bt_k4 * 4 + 1) * BPITCH + n] = f2tf32f(v.y);
                Bs[0][(bt_k4 * 4 + 2) * BPITCH + n] = f2tf32f(v.z);
                Bs[0][(bt_k4 * 4 + 3) * BPITCH + n] = f2tf32f(v.w);
            }
        } else {
#pragma unroll
            for (int i = 0; i < 4; i++) {
                int kk = bn_kr + 8 * i;
                float4 v = *(const float4*)&Bm[(long)(k0 + kk) * ldb + n0 + bn_n4 * 4];
                float4 w = make_float4(f2tf32f(v.x), f2tf32f(v.y), f2tf32f(v.z), f2tf32f(v.w));
                *(float4*)&Bs[0][kk * BPITCH + bn_n4 * 4] = w;
            }
        }
    }
    __syncthreads();

    int buf = 0;
    for (int it = 0; it < niter; it++) {
        float4 ra[4], rb[4];
        const bool more = (it + 1 < niter);
        if (more) {
            const int k0 = (it + 1) << 5;
#pragma unroll
            for (int i = 0; i < 4; i++) {
                int m = a_mr + 16 * i;
                ra[i] = *(const float4*)&A[(long)(m0 + m) * lda + k0 + a_k4 * 4];
            }
            if (TRANSB) {
#pragma unroll
                for (int i = 0; i < 4; i++) {
                    int n = bt_nr + 16 * i;
                    rb[i] = *(const float4*)&Bm[(long)(n0 + n) * ldb + k0 + bt_k4 * 4];
                }
            } else {
#pragma unroll
                for (int i = 0; i < 4; i++) {
                    int kk = bn_kr + 8 * i;
                    rb[i] = *(const float4*)&Bm[(long)(k0 + kk) * ldb + n0 + bn_n4 * 4];
                }
            }
        }

        // ---- compute on buf ----
#pragma unroll
        for (int ks = 0; ks < 4; ks++) {
            unsigned af[2][4];
#pragma unroll
            for (int im = 0; im < 2; im++) {
                int mb = wm * 32 + im * 16;
                af[im][0] = __float_as_uint(As[buf][(mb + g) * APITCH + ks * 8 + tg]);
                af[im][1] = __float_as_uint(As[buf][(mb + 8 + g) * APITCH + ks * 8 + tg]);
                af[im][2] = __float_as_uint(As[buf][(mb + g) * APITCH + ks * 8 + 4 + tg]);
                af[im][3] = __float_as_uint(As[buf][(mb + 8 + g) * APITCH + ks * 8 + 4 + tg]);
            }
            unsigned bf[4][2];
#pragma unroll
            for (int in = 0; in < 4; in++) {
                int nb = wn * 32 + in * 8;
                bf[in][0] = __float_as_uint(Bs[buf][(ks * 8 + tg) * BPITCH + nb + g]);
                bf[in][1] = __float_as_uint(Bs[buf][(ks * 8 + 4 + tg) * BPITCH + nb + g]);
            }
#pragma unroll
            for (int im = 0; im < 2; im++)
#pragma unroll
                for (int in = 0; in < 4; in++) {
                    asm volatile(
                        "mma.sync.aligned.m16n8k8.row.col.f32.tf32.tf32.f32 "
                        "{%0,%1,%2,%3}, {%4,%5,%6,%7}, {%8,%9}, {%0,%1,%2,%3};"
                        : "+f"(acc[im][in][0]), "+f"(acc[im][in][1]),
                          "+f"(acc[im][in][2]), "+f"(acc[im][in][3])
                        : "r"(af[im][0]), "r"(af[im][1]), "r"(af[im][2]), "r"(af[im][3]),
                          "r"(bf[in][0]), "r"(bf[in][1]));
                }
        }

        if (more) {
            int nb = buf ^ 1;
#pragma unroll
            for (int i = 0; i < 4; i++) {
                int m = a_mr + 16 * i;
                float4 w = make_float4(f2tf32f(ra[i].x), f2tf32f(ra[i].y),
                                       f2tf32f(ra[i].z), f2tf32f(ra[i].w));
                *(float4*)&As[nb][m * APITCH + a_k4 * 4] = w;
            }
            if (TRANSB) {
#pragma unroll
                for (int i = 0; i < 4; i++) {
                    int n = bt_nr + 16 * i;
                    Bs[nb][(bt_k4 * 4 + 0) * BPITCH + n] = f2tf32f(rb[i].x);
                    Bs[nb][(bt_k4 * 4 + 1) * BPITCH + n] = f2tf32f(rb[i].y);
                    Bs[nb][(bt_k4 * 4 + 2) * BPITCH + n] = f2tf32f(rb[i].z);
                    Bs[nb][(bt_k4 * 4 + 3) * BPITCH + n] = f2tf32f(rb[i].w);
                }
            } else {
#pragma unroll
                for (int i = 0; i < 4; i++) {
                    int kk = bn_kr + 8 * i;
                    float4 w = make_float4(f2tf32f(rb[i].x), f2tf32f(rb[i].y),
                                           f2tf32f(rb[i].z), f2tf32f(rb[i].w));
                    *(float4*)&Bs[nb][kk * BPITCH + bn_n4 * 4] = w;
                }
            }
        }
        __syncthreads();
        buf ^= 1;
    }

    // ---- epilogue ----
#pragma unroll
    for (int im = 0; im < 2; im++) {
        int r0 = m0 + wm * 32 + im * 16 + g;
        int r1 = r0 + 8;
#pragma unroll
        for (int in = 0; in < 4; in++) {
            int c = n0 + wn * 32 + in * 8 + 2 * tg;
            float b0 = 0.f, b1 = 0.f;
            if (BIAS) { b0 = bias[c]; b1 = bias[c + 1]; }
            float2 v0 = make_float2(acc[im][in][0] + b0, acc[im][in][1] + b1);
            float2 v1 = make_float2(acc[im][in][2] + b0, acc[im][in][3] + b1);
            *(float2*)&C[(long)r0 * ldc + c] = v0;
            *(float2*)&C[(long)r1 * ldc + c] = v1;
        }
    }
}

// ---------------- s_i, s_j : per (b,h,n) dot over DH ----------------
__global__ void sij_kernel(const float* __restrict__ attn)
{
    int gw = (blockIdx.x * blockDim.x + threadIdx.x) >> 5;
    int lane = threadIdx.x & 31;
    if (gw >= BB * HEADS * NN_NODES) return;
    int b = gw / (HEADS * NN_NODES);
    int r = gw % (HEADS * NN_NODES);
    int h = r / NN_NODES;
    int n = r % NN_NODES;
    const float* hp = g_hp + ((long)(b * NN_NODES + n)) * FDIM + h * DH;
    const float* ai = attn + h * 2 * DH;
    float si = 0.f, sj = 0.f;
#pragma unroll
    for (int d = lane; d < DH; d += 32) {
        float v = hp[d];
        si += v * ai[d];
        sj += v * ai[DH + d];
    }
#pragma unroll
    for (int o = 16; o > 0; o >>= 1) {
        si += __shfl_down_sync(0xffffffffu, si, o);
        sj += __shfl_down_sync(0xffffffffu, sj, o);
    }
    if (lane == 0) { g_si[gw] = si; g_sj[gw] = sj; }
}

// ---------------- fused attention softmax + aggregation ----------------
__global__ void attn_kernel()
{
    __shared__ float sj[NN_NODES];
    __shared__ float w[16][NN_NODES];
    __shared__ float red[8];
    int bh = blockIdx.y;
    int b = bh / HEADS, h = bh % HEADS;
    int i0 = blockIdx.x * 16;
    int tid = threadIdx.x;

    for (int j = tid; j < NN_NODES; j += 256) sj[j] = g_sj[bh * NN_NODES + j];
    __syncthreads();

    float mx = -3.4e38f;
    for (int j = tid; j < NN_NODES; j += 256) mx = fmaxf(mx, sj[j]);
#pragma unroll
    for (int o = 16; o > 0; o >>= 1) mx = fmaxf(mx, __shfl_xor_sync(0xffffffffu, mx, o));
    if ((tid & 31) == 0) red[tid >> 5] = mx;
    __syncthreads();
    if (tid == 0) {
        float m = red[0];
        for (int q = 1; q < 8; q++) m = fmaxf(m, red[q]);
        red[0] = m;
    }
    __syncthreads();
    float sjmax = red[0];

    int wi = tid >> 5, lane = tid & 31;
#pragma unroll
    for (int rr = 0; rr < 2; rr++) {
        int r = wi * 2 + rr;
        int i = i0 + r;
        float si = g_si[bh * NN_NODES + i];
        float M = si + sjmax;
        M = (M >= 0.f) ? M : 0.2f * M;
        float sum = 0.f;
        for (int j = lane; j < NN_NODES; j += 32) {
            float e = si + sj[j];
            e = (e >= 0.f) ? e : 0.2f * e;
            float p = expf(e - M);
            w[r][j] = p;
            sum += p;
        }
#pragma unroll
        for (int o = 16; o > 0; o >>= 1) sum += __shfl_xor_sync(0xffffffffu, sum, o);
        float inv = 1.0f / sum;
        for (int j = lane; j < NN_NODES; j += 32) w[r][j] *= inv;
    }
    __syncthreads();

    int d = tid;
    const float* hp = g_hp + (long)(b * NN_NODES) * FDIM + h * DH + d;
    float acc[16];
#pragma unroll
    for (int r = 0; r < 16; r++) acc[r] = 0.f;
    for (int j = 0; j < NN_NODES; j++) {
        float v = hp[(long)j * FDIM];
#pragma unroll
        for (int r = 0; r < 16; r++) acc[r] += w[r][j] * v;
    }
#pragma unroll
    for (int r = 0; r < 16; r++)
        g_nf[((long)(b * NN_NODES) + i0 + r) * FDIM + h * DH + d] = acc[r];
}

// ---------------- edge MLP scores ----------------
__global__ void edge_kernel(const float* __restrict__ b1,
                            const float* __restrict__ w2,
                            const float* __restrict__ b2p)
{
    __shared__ float spi[16][257];
    __shared__ float spj[16][257];
    __shared__ float sb1[AH];
    __shared__ float sw2[AH];
    int b = blockIdx.z;
    int i0 = blockIdx.y * 16, j0 = blockIdx.x * 16;
    int tid = threadIdx.x;
    if (tid < AH) { sb1[tid] = b1[tid]; sw2[tid] = w2[tid]; }
#pragma unroll
    for (int l = 0; l < 16; l++) {
        spi[l][tid] = g_pi[((long)(b * NN_NODES) + i0 + l) * AH + tid];
        spj[l][tid] = g_pj[((long)(b * NN_NODES) + j0 + l) * AH + tid];
    }
    __syncthreads();
    int ti = tid >> 4, tj = tid & 15;
    float acc = 0.f;
#pragma unroll 8
    for (int a = 0; a < AH; a++) {
        float t = spi[ti][a] + spj[tj][a] + sb1[a];
        acc += fmaxf(t, 0.f) * sw2[a];
    }
    float sc = (acc + b2p[0]) * 2.0f;   // /TEMP
    g_sc[(long)b * NN2 + (long)(i0 + ti) * NN_NODES + (j0 + tj)] = sc;
}

// ---------------- softmax reductions (deterministic) ----------------
__global__ void redmax_stage1()
{
    int b = blockIdx.y, blk = blockIdx.x, tid = threadIdx.x;
    const float* p = g_sc + (long)b * NN2;
    float mx = -3.4e38f;
    for (int i = blk * 256 + tid; i < NN2; i += 256 * 256) mx = fmaxf(mx, p[i]);
    __shared__ float sh[256];
    sh[tid] = mx; __syncthreads();
    for (int s = 128; s > 0; s >>= 1) { if (tid < s) sh[tid] = fmaxf(sh[tid], sh[tid + s]); __syncthreads(); }
    if (tid == 0) g_part[b * 256 + blk] = sh[0];
}
__global__ void redmax_stage2()
{
    int b = blockIdx.x, tid = threadIdx.x;
    __shared__ float sh[256];
    sh[tid] = g_part[b * 256 + tid]; __syncthreads();
    for (int s = 128; s > 0; s >>= 1) { if (tid < s) sh[tid] = fmaxf(sh[tid], sh[tid + s]); __syncthreads(); }
    if (tid == 0) g_mx[b] = sh[0];
}
__global__ void exp_stage1()
{
    int b = blockIdx.y, blk = blockIdx.x, tid = threadIdx.x;
    float* p = g_sc + (long)b * NN2;
    float mx = g_mx[b];
    float s = 0.f;
    for (int i = blk * 256 + tid; i < NN2; i += 256 * 256) {
        float v = expf(p[i] - mx);
        p[i] = v;
        s += v;
    }
    __shared__ float sh[256];
    sh[tid] = s; __syncthreads();
    for (int q = 128; q > 0; q >>= 1) { if (tid < q) sh[tid] += sh[tid + q]; __syncthreads(); }
    if (tid == 0) g_part[b * 256 + blk] = sh[0];
}
__global__ void sum_stage2()
{
    int b = blockIdx.x, tid = threadIdx.x;
    __shared__ float sh[256];
    sh[tid] = g_part[b * 256 + tid]; __syncthreads();
    for (int q = 128; q > 0; q >>= 1) { if (tid < q) sh[tid] += sh[tid + q]; __syncthreads(); }
    if (tid == 0) g_S[b] = sh[0];
}
// NOTE: explicit normalization pass removed — top-k selection is scale
// invariant and S cancels in the final renormalization (eps scaled by S).

// ---------------- radix select: chip-wide histogram per pass ----------------
__global__ void sel_init_kernel()
{
    int tid = threadIdx.x; // 512
    if (tid < 256) { g_hist[0][tid] = 0u; g_hist[1][tid] = 0u; }
    if (tid < BB) { g_selpref[tid] = 0u; g_selrank[tid] = THR_IDX; }
}
__global__ void sel_hist_kernel(int pass)
{
    __shared__ unsigned hist[256];
    int b = blockIdx.y, blk = blockIdx.x, tid = threadIdx.x;
    hist[tid] = 0u;
    __syncthreads();
    int shift = pass * 8;
    unsigned pref = g_selpref[b];
    unsigned mask = (pass == 3) ? 0u : (0xFFFFFFFFu << (shift + 8));
    const float* sm = g_sc + (long)b * NN2;
    for (int i = blk * 256 + tid; i < NN2; i += 32 * 256) {
        unsigned v = __float_as_uint(sm[i]);
        if ((v & mask) == pref) atomicAdd(&hist[(v >> shift) & 255], 1u);
    }
    __syncthreads();
    if (hist[tid]) atomicAdd(&g_hist[b][tid], hist[tid]);
}
__global__ void sel_pick_kernel(int pass)
{
    __shared__ unsigned sh[256];
    int b = blockIdx.x, tid = threadIdx.x;
    sh[tid] = g_hist[b][tid];
    g_hist[b][tid] = 0u;   // reset for next pass
    __syncthreads();
    if (tid == 0) {
        int shift = pass * 8;
        int rank = g_selrank[b];
        unsigned cum = 0; int bsel = 0;
        for (int x = 0; x < 256; x++) {
            if (cum + sh[x] > (unsigned)rank) { bsel = x; break; }
            cum += sh[x];
        }
        g_selrank[b] = rank - (int)cum;
        unsigned pref = g_selpref[b] | ((unsigned)bsel << shift);
        g_selpref[b] = pref;
        if (pass == 0) g_thr[b] = __uint_as_float(pref);
    }
}

__global__ void thresh_stage1()
{
    int b = blockIdx.y, blk = blockIdx.x, tid = threadIdx.x;
    const float* sm = g_sc + (long)b * NN2;
    float* adj = g_adj + (long)b * NN2;
    float thr = g_thr[b];
    float s = 0.f;
    for (int i = blk * 256 + tid; i < NN2; i += 256 * 256) {
        float v = sm[i];
        float keep = (v >= thr) ? v : 0.f;
        adj[i] = keep;
        s += keep;
    }
    __shared__ float sh[256];
    sh[tid] = s; __syncthreads();
    for (int q = 128; q > 0; q >>= 1) { if (tid < q) sh[tid] += sh[tid + q]; __syncthreads(); }
    if (tid == 0) g_part[b * 256 + blk] = sh[0];
}
__global__ void selsum_stage2()
{
    int b = blockIdx.x, tid = threadIdx.x;
    __shared__ float sh[256];
    sh[tid] = g_part[b * 256 + tid]; __syncthreads();
    for (int q = 128; q > 0; q >>= 1) { if (tid < q) sh[tid] += sh[tid + q]; __syncthreads(); }
    if (tid == 0) g_selsum[b] = sh[0];
}
__global__ void adjnorm_kernel()
{
    int b = blockIdx.y, blk = blockIdx.x, tid = threadIdx.x;
    float* adj = g_adj + (long)b * NN2;
    // cm = kept/S divided by (sum(kept)/S + 1e-12)  ==  kept / (keptsum + 1e-12*S)
    float denom = g_selsum[b] + 1e-12f * g_S[b];
    float inv = 1.0f / denom;
    for (int i = blk * 256 + tid; i < NN2; i += 256 * 256) adj[i] = adj[i] * inv;
}

// ---------------- batchnorm + relu ----------------
__global__ void bn_relu_kernel(float* __restrict__ h,
                               const float* __restrict__ ga,
                               const float* __restrict__ be, int C)
{
    __shared__ float sh[8][32], sh2[8][32];
    int c = blockIdx.x * 32 + threadIdx.x;
    int ry = threadIdx.y;
    float s = 0.f, s2 = 0.f;
    for (int r = ry; r < BN_M; r += 8) {
        float v = h[(long)r * C + c];
        s += v; s2 += v * v;
    }
    sh[ry][threadIdx.x] = s; sh2[ry][threadIdx.x] = s2;
    __syncthreads();
    if (ry == 0) {
        for (int r = 1; r < 8; r++) { s += sh[r][threadIdx.x]; s2 += sh2[r][threadIdx.x]; }
        float m = s / (float)BN_M;
        float v = s2 / (float)BN_M - m * m;
        sh[0][threadIdx.x] = m;
        sh2[0][threadIdx.x] = rsqrtf(v + 1e-5f);
    }
    __syncthreads();
    float m = sh[0][threadIdx.x], inv = sh2[0][threadIdx.x];
    float gg = ga[c], bb = be[c];
    for (int r = ry; r < BN_M; r += 8) {
        float v = h[(long)r * C + c];
        h[(long)r * C + c] = fmaxf((v - m) * inv * gg + bb, 0.f);
    }
}

// ---------------- mean pool + classifier ----------------
__global__ void head_kernel(const float* __restrict__ cls_w,
                            const float* __restrict__ cls_b,
                            float* __restrict__ out)
{
    __shared__ float feat[OUTF];
    int b = blockIdx.x, tid = threadIdx.x; // 128 threads
    float s = 0.f;
    for (int r = 0; r < NN_NODES; r++) s += g_h2b[((long)b * NN_NODES + r) * OUTF + tid];
    feat[tid] = s / (float)NN_NODES;
    __syncthreads();
    if (tid < NCLS) {
        float acc = cls_b[tid];
        for (int f = 0; f < OUTF; f++) acc += feat[f] * cls_w[tid * OUTF + f];
        out[b * NCLS + tid] = acc;
    }
}

// ---------------- launcher ----------------
extern "C" void kernel_launch(void* const* d_in, const int* in_sizes, int n_in,
                              void* d_out, int out_size)
{
    const float* x     = (const float*)d_in[0];
    const float* Wg    = (const float*)d_in[1];
    const float* attn  = (const float*)d_in[2];
    const float* W1    = (const float*)d_in[3];
    const float* b1    = (const float*)d_in[4];
    const float* w2    = (const float*)d_in[5];
    const float* b2    = (const float*)d_in[6];
    const float* gc1_w = (const float*)d_in[7];
    const float* gc1_b = (const float*)d_in[8];
    const float* bn1_g = (const float*)d_in[9];
    const float* bn1_b = (const float*)d_in[10];
    const float* gc2_w = (const float*)d_in[11];
    const float* gc2_b = (const float*)d_in[12];
    const float* bn2_g = (const float*)d_in[13];
    const float* bn2_b = (const float*)d_in[14];
    const float* cls_w = (const float*)d_in[15];
    const float* cls_b = (const float*)d_in[16];
    float* out = (float*)d_out;

    float *hp, *nf, *pi, *pj, *adj, *h1, *h1b, *h2, *h2b;
    cudaGetSymbolAddress((void**)&hp,  g_hp);
    cudaGetSymbolAddress((void**)&nf,  g_nf);
    cudaGetSymbolAddress((void**)&pi,  g_pi);
    cudaGetSymbolAddress((void**)&pj,  g_pj);
    cudaGetSymbolAddress((void**)&adj, g_adj);
    cudaGetSymbolAddress((void**)&h1,  g_h1);
    cudaGetSymbolAddress((void**)&h1b, g_h1b);
    cudaGetSymbolAddress((void**)&h2,  g_h2);
    cudaGetSymbolAddress((void**)&h2b, g_h2b);

    // 1) hp = x @ Wg^T   (1024 x 1024 x 1024)
    mma_gemm<true, false><<<dim3(FDIM / 64, (BB * NN_NODES) / 64, 1), 128>>>(
        x, FDIM, 0, Wg, FDIM, 0, nullptr, hp, FDIM, 0, FDIM);

    // 2) s_i, s_j
    sij_kernel<<<(BB * HEADS * NN_NODES * 32 + 255) / 256, 256>>>(attn);

    // 3) attention softmax + aggregate
    attn_kernel<<<dim3(NN_NODES / 16, BB * HEADS), 256>>>();

    // 4) pi / pj
    mma_gemm<true, false><<<dim3(AH / 64, (BB * NN_NODES) / 64, 1), 128>>>(
        nf, FDIM, 0, W1, 2 * FDIM, 0, nullptr, pi, AH, 0, FDIM);
    mma_gemm<true, false><<<dim3(AH / 64, (BB * NN_NODES) / 64, 1), 128>>>(
        nf, FDIM, 0, W1 + FDIM, 2 * FDIM, 0, nullptr, pj, AH, 0, FDIM);

    // 5) edge scores
    edge_kernel<<<dim3(NN_NODES / 16, NN_NODES / 16, BB), 256>>>(b1, w2, b2);

    // 6) flat softmax (no normalization pass needed)
    redmax_stage1<<<dim3(256, BB), 256>>>();
    redmax_stage2<<<BB, 256>>>();
    exp_stage1<<<dim3(256, BB), 256>>>();
    sum_stage2<<<BB, 256>>>();

    // 7) exact k-th statistic on unnormalized exp values + renormalize
    sel_init_kernel<<<1, 512>>>();
    for (int pass = 3; pass >= 0; pass--) {
        sel_hist_kernel<<<dim3(32, BB), 256>>>(pass);
        sel_pick_kernel<<<BB, 256>>>(pass);
    }
    thresh_stage1<<<dim3(256, BB), 256>>>();
    selsum_stage2<<<BB, 256>>>();
    adjnorm_kernel<<<dim3(256, BB), 256>>>();

    // 8) h1 = adj @ nf
    mma_gemm<false, false><<<dim3(FDIM / 64, NN_NODES / 64, BB), 128>>>(
        adj, NN_NODES, (long)NN2, nf, FDIM, (long)NN_NODES * FDIM, nullptr,
        h1, FDIM, (long)NN_NODES * FDIM, NN_NODES);

    // 9) h1b = h1 @ gc1_w^T + gc1_b
    mma_gemm<true, true><<<dim3(HID / 64, (BB * NN_NODES) / 64, 1), 128>>>(
        h1, FDIM, 0, gc1_w, FDIM, 0, gc1_b, h1b, HID, 0, FDIM);

    // 10) bn1 + relu
    bn_relu_kernel<<<HID / 32, dim3(32, 8)>>>(h1b, bn1_g, bn1_b, HID);

    // 11) h2 = adj @ h1b
    mma_gemm<false, false><<<dim3(HID / 64, NN_NODES / 64, BB), 128>>>(
        adj, NN_NODES, (long)NN2, h1b, HID, (long)NN_NODES * HID, nullptr,
        h2, HID, (long)NN_NODES * HID, NN_NODES);

    // 12) h2b = h2 @ gc2_w^T + gc2_b
    mma_gemm<true, true><<<dim3(OUTF / 64, (BB * NN_NODES) / 64, 1), 128>>>(
        h2, HID, 0, gc2_w, HID, 0, gc2_b, h2b, OUTF, 0, HID);

    // 13) bn2 + relu
    bn_relu_kernel<<<OUTF / 32, dim3(32, 8)>>>(h2b, bn2_g, bn2_b, OUTF);

    // 14) mean pool + classifier
    head_kernel<<<BB, OUTF>>>(cls_w, cls_b, out);
}